// round 2
// baseline (speedup 1.0000x reference)
#include <cuda_runtime.h>
#include <cstdint>

#define BB 256
#define CC 768
#define LL 256
#define PP 3
#define MINUS_F (-100.0f)

#define ROWS_PER_BLOCK 64
#define NWARPS 8
#define THREADS (NWARPS * 32)

// Flag: 1 => mask buffer is int64 (little-endian low word holds the value),
//       0 => mask buffer is int32.
__device__ int g_mask_is_64;

__global__ void pm_reset_flag() { g_mask_is_64 = 1; }

// The int32 view of the first 65536 ints (256KB) is safe for both dtypes:
//  - int32 mask: exactly 65536 ints; odd slots are mask values at odd l
//    (random in 0..3, virtually certainly some nonzero).
//  - int64 mask: 131072 ints total; first 65536 ints cover the first 32768
//    logical values; odd slots are high words == 0 for values in [0,3].
__global__ void pm_detect(const int* __restrict__ m) {
    int i = blockIdx.x * blockDim.x + threadIdx.x;   // over 32768 odd slots
    if (i < (BB * LL) / 2) {
        if (m[2 * i + 1] != 0) g_mask_is_64 = 0;
    }
}

__global__ __launch_bounds__(THREADS) void piece_max_pool_kernel(
    const float* __restrict__ x,
    const int* __restrict__ m32,
    float* __restrict__ out)
{
    const int b    = blockIdx.x;
    const int c0   = blockIdx.y * ROWS_PER_BLOCK;
    const int warp = threadIdx.x >> 5;
    const int lane = threadIdx.x & 31;

    const bool is64 = (g_mask_is_64 != 0);

    // Per-lane mask values for this lane's 8 fixed L positions:
    //   l = h*128 + lane*4 + j,  h in {0,1}, j in {0..3}
    int mv[8];
    const int base = b * LL;
#pragma unroll
    for (int h = 0; h < 2; ++h) {
#pragma unroll
        for (int j = 0; j < 4; ++j) {
            const int l   = h * 128 + lane * 4 + j;
            const int idx = base + l;
            mv[h * 4 + j] = is64 ? m32[2 * idx] : m32[idx];
        }
    }

#pragma unroll
    for (int i = 0; i < ROWS_PER_BLOCK / NWARPS; ++i) {
        const int c = c0 + i * NWARPS + warp;   // consecutive warps -> adjacent rows
        const float4* xp = reinterpret_cast<const float4*>(
            x + (size_t)(b * CC + c) * LL);

        const float4 v0 = xp[lane];        // l = lane*4 .. lane*4+3
        const float4 v1 = xp[32 + lane];   // l = 128 + lane*4 ..

        float g  = -1e30f;
        float a0 = -1e30f, a1 = -1e30f, a2 = -1e30f;

        const float vv[8] = {v0.x, v0.y, v0.z, v0.w, v1.x, v1.y, v1.z, v1.w};
#pragma unroll
        for (int j = 0; j < 8; ++j) {
            const float v = vv[j];
            g = fmaxf(g, v);
            if (mv[j] == 1)      a0 = fmaxf(a0, v);
            else if (mv[j] == 2) a1 = fmaxf(a1, v);
            else if (mv[j] == 3) a2 = fmaxf(a2, v);
        }

        // Butterfly reduce the 4 maxima across the warp.
#pragma unroll
        for (int s = 16; s > 0; s >>= 1) {
            g  = fmaxf(g,  __shfl_xor_sync(0xFFFFFFFFu, g,  s));
            a0 = fmaxf(a0, __shfl_xor_sync(0xFFFFFFFFu, a0, s));
            a1 = fmaxf(a1, __shfl_xor_sync(0xFFFFFFFFu, a1, s));
            a2 = fmaxf(a2, __shfl_xor_sync(0xFFFFFFFFu, a2, s));
        }

        if (lane < PP) {
            const float a = (lane == 0) ? a0 : ((lane == 1) ? a1 : a2);
            out[(size_t)b * (PP * CC) + lane * CC + c] = fmaxf(a, g + MINUS_F);
        }
    }
}

extern "C" void kernel_launch(void* const* d_in, const int* in_sizes, int n_in,
                              void* d_out, int out_size)
{
    const float* x = (const float*)d_in[0];
    const int*   m = (const int*)d_in[1];   // int32 view of mask buffer
    float* out = (float*)d_out;

    pm_reset_flag<<<1, 1>>>();
    pm_detect<<<(BB * LL / 2 + 255) / 256, 256>>>(m);

    dim3 grid(BB, CC / ROWS_PER_BLOCK);
    piece_max_pool_kernel<<<grid, THREADS>>>(x, m, out);
}